// round 8
// baseline (speedup 1.0000x reference)
#include <cuda_runtime.h>
#include <cuda_fp16.h>
#include <math.h>
#include <stdint.h>

#define D_MODEL 4096
#define N_EXP   64
#define ROWS    16384          // 4 * 4096
#define LN_EPS  1e-5f
#define TM      128            // rows per CTA
#define KC      128            // K per stage
#define NSTAGE  (D_MODEL / KC) // 32
#define NCTA    (ROWS / TM)    // 128
#define THREADS 512

// Output layout (fp32 flat): sparse_w[16384*64], indices[16384*2] as float, lb_loss
#define OUT_IDX_OFF 1048576
#define OUT_LB_OFF  1081344

// ---- dynamic smem layout ----
#define A_STR 272                    // 128 halves + 8 pad, bytes per row
#define AH_O  0
#define AM_O  (TM * A_STR)           // 34816
#define BH_O  (2 * AM_O)             // 69632
#define BM_O  (BH_O + N_EXP * A_STR) // 87040
#define BUFB  (BM_O + N_EXP * A_STR) // 104448
#define EXT   (2 * BUFB)             // 208896
#define MU_O  (EXT)
#define RS_O  (EXT + 512)
#define C1_O  (EXT + 1024)
#define C2_O  (EXT + 1280)
#define SMEM_REQ (EXT + 1536)        // 210432 bytes

// ---- device scratch ----
__device__ __align__(16) __half g_wh[N_EXP * D_MODEL];  // high fp16 part of gamma*W
__device__ __align__(16) __half g_wm[N_EXP * D_MODEL];  // mid  fp16 part
__device__ float g_c1p[256];
__device__ float g_c2p[256];
__device__ float g_part[NCTA * N_EXP];

// ================= PTX helpers =================
__device__ __forceinline__ uint32_t smem_u32(const void* p) {
    uint32_t a;
    asm("{ .reg .u64 t; cvta.to.shared.u64 t, %1; cvt.u32.u64 %0, t; }" : "=r"(a) : "l"(p));
    return a;
}
__device__ __forceinline__ void ldsm4(uint32_t* r, uint32_t addr) {
    asm volatile("ldmatrix.sync.aligned.m8n8.x4.shared.b16 {%0,%1,%2,%3}, [%4];"
                 : "=r"(r[0]), "=r"(r[1]), "=r"(r[2]), "=r"(r[3]) : "r"(addr));
}
__device__ __forceinline__ void mma16816(float* c, const uint32_t* a, const uint32_t* b) {
    asm volatile(
        "mma.sync.aligned.m16n8k16.row.col.f32.f16.f16.f32 "
        "{%0,%1,%2,%3}, {%4,%5,%6,%7}, {%8,%9}, {%0,%1,%2,%3};"
        : "+f"(c[0]), "+f"(c[1]), "+f"(c[2]), "+f"(c[3])
        : "r"(a[0]), "r"(a[1]), "r"(a[2]), "r"(a[3]), "r"(b[0]), "r"(b[1]));
}
__device__ __forceinline__ uint32_t cvt_h2(float lo, float hi) {
    uint32_t r;
    asm("cvt.rn.f16x2.f32 %0, %1, %2;" : "=r"(r) : "f"(hi), "f"(lo));
    return r;
}
__device__ __forceinline__ void cpa16(uint32_t dst, const __half* src) {
    uint64_t g;
    asm("cvta.to.global.u64 %0, %1;" : "=l"(g) : "l"(src));
    asm volatile("cp.async.ca.shared.global [%0], [%1], 16;" :: "r"(dst), "l"(g) : "memory");
}
#define CP_COMMIT() asm volatile("cp.async.commit_group;" ::: "memory")
#define CP_WAIT0()  asm volatile("cp.async.wait_group 0;" ::: "memory")

// ================= prep: split gamma*W into fp16 h/m parts + partial c1/c2 =================
__global__ void prep_kernel(const float* __restrict__ W,
                            const float* __restrict__ gamma,
                            const float* __restrict__ beta,
                            const float* __restrict__ b) {
    int blk = blockIdx.x;          // 256 blocks: expert e = blk>>2, quarter q = blk&3
    int e = blk >> 2, q = blk & 3;
    int t = threadIdx.x;           // 256
    float a1 = 0.f, a2 = 0.f;
    #pragma unroll
    for (int i = 0; i < 4; ++i) {
        int k = q * 1024 + i * 256 + t;
        float w  = W[e * D_MODEL + k];
        float gw = gamma[k] * w;
        a1 += gw;
        a2 += beta[k] * w;
        __half h = __float2half_rn(gw);
        float  r = gw - __half2float(h);
        __half m = __float2half_rn(r);
        g_wh[e * D_MODEL + k] = h;
        g_wm[e * D_MODEL + k] = m;
    }
    __shared__ float s1[8], s2[8];
    #pragma unroll
    for (int o = 16; o > 0; o >>= 1) {
        a1 += __shfl_xor_sync(0xffffffffu, a1, o);
        a2 += __shfl_xor_sync(0xffffffffu, a2, o);
    }
    if ((t & 31) == 0) { s1[t >> 5] = a1; s2[t >> 5] = a2; }
    __syncthreads();
    if (t == 0) {
        float v1 = 0.f, v2 = 0.f;
        #pragma unroll
        for (int i = 0; i < 8; ++i) { v1 += s1[i]; v2 += s2[i]; }
        g_c1p[blk] = v1;
        g_c2p[blk] = v2 + (q == 0 ? b[e] : 0.f);
    }
}

// ================= main fused kernel =================
extern __shared__ char smem_dyn[];

__global__ __launch_bounds__(THREADS, 1)
void main_kernel(const float* __restrict__ x, float* __restrict__ out) {
    char* smb = smem_dyn;
    const uint32_t sbase = smem_u32(smb);
    const int t    = threadIdx.x;
    const int lane = t & 31;
    const int wid  = t >> 5;
    const int wm   = wid & 7;       // M block (16 rows)
    const int wn   = wid >> 3;      // N block (32 cols)
    const int row0 = blockIdx.x * TM;

    if (t < 64) {
        float c1 = g_c1p[4 * t] + g_c1p[4 * t + 1] + g_c1p[4 * t + 2] + g_c1p[4 * t + 3];
        float c2 = g_c2p[4 * t] + g_c2p[4 * t + 1] + g_c2p[4 * t + 2] + g_c2p[4 * t + 3];
        ((float*)(smb + C1_O))[t] = c1;
        ((float*)(smb + C2_O))[t] = c2;
    }

    // producer mapping: 4 threads per row (32 cols each per stage)
    const int pr = t >> 2, p4 = t & 3;
    const float4* xp = (const float4*)(x + (size_t)(row0 + pr) * D_MODEL) + p4 * 8;
    // B cp.async mapping: 8 threads per expert row
    const int be = t >> 3, btc = t & 7;
    const __half* bsrc_h = g_wh + (size_t)be * D_MODEL + btc * 16;
    const __half* bsrc_m = g_wm + (size_t)be * D_MODEL + btc * 16;
    const uint32_t bdst = (uint32_t)(be * A_STR + btc * 32);

    // ldmatrix lane offsets
    const uint32_t aoff = (uint32_t)((wm * 16 + (lane & 15)) * A_STR + (lane >> 4) * 16);
    const uint32_t boff = (uint32_t)((wn * 32 + ((lane >> 4) & 1) * 8 + (lane & 7)) * A_STR
                                     + ((lane >> 3) & 1) * 16);
    const uint32_t a_sts = (uint32_t)(pr * A_STR + p4 * 64);

    float acc[4][4];
    #pragma unroll
    for (int ni = 0; ni < 4; ++ni)
        #pragma unroll
        for (int q = 0; q < 4; ++q) acc[ni][q] = 0.f;

    float ls = 0.f, lss = 0.f;
    float4 cx[8];

    // ---- prologue: B(0) cp.async, x(0) split+STS, prefetch x(1) ----
    {
        uint32_t bu = sbase;
        cpa16(bu + BH_O + bdst,      bsrc_h);
        cpa16(bu + BH_O + bdst + 16, bsrc_h + 8);
        cpa16(bu + BM_O + bdst,      bsrc_m);
        cpa16(bu + BM_O + bdst + 16, bsrc_m + 8);
        CP_COMMIT();

        #pragma unroll
        for (int j = 0; j < 8; ++j) cx[j] = xp[j];
        char* bb = smb;
        #pragma unroll
        for (int g = 0; g < 4; ++g) {
            float4 a = cx[2 * g], c = cx[2 * g + 1];
            float f[8] = {a.x, a.y, a.z, a.w, c.x, c.y, c.z, c.w};
            uint32_t hp[4], mp[4];
            #pragma unroll
            for (int i = 0; i < 4; ++i) {
                float f0 = f[2 * i], f1 = f[2 * i + 1];
                uint32_t h2 = cvt_h2(f0, f1);
                __half2 hh = *(__half2*)&h2;
                float2 bk = __half22float2(hh);
                mp[i] = cvt_h2(f0 - bk.x, f1 - bk.y);
                hp[i] = h2;
                ls  += f0 + f1;
                lss  = fmaf(f0, f0, fmaf(f1, f1, lss));
            }
            *(uint4*)(bb + AH_O + a_sts + g * 16) = make_uint4(hp[0], hp[1], hp[2], hp[3]);
            *(uint4*)(bb + AM_O + a_sts + g * 16) = make_uint4(mp[0], mp[1], mp[2], mp[3]);
        }
        #pragma unroll
        for (int j = 0; j < 8; ++j) cx[j] = xp[32 + j];
        CP_WAIT0();
    }
    __syncthreads();

    // ---- main loop: cp.async B(s+1) || MMA(s) || split+STS x(s+1) || LDG x(s+2) ----
    for (int s = 0; s < NSTAGE; ++s) {
        const uint32_t rb = sbase + (uint32_t)((s & 1) * BUFB);
        const uint32_t wb = sbase + (uint32_t)(((s + 1) & 1) * BUFB);
        char* wbuf = smb + ((s + 1) & 1) * BUFB;

        if (s + 1 < NSTAGE) {
            const __half* sh = bsrc_h + (s + 1) * KC;
            const __half* sm = bsrc_m + (s + 1) * KC;
            cpa16(wb + BH_O + bdst,      sh);
            cpa16(wb + BH_O + bdst + 16, sh + 8);
            cpa16(wb + BM_O + bdst,      sm);
            cpa16(wb + BM_O + bdst + 16, sm + 8);
            CP_COMMIT();
        }

        const uint32_t abh = rb + AH_O + aoff;
        const uint32_t abm = rb + AM_O + aoff;
        const uint32_t bbh = rb + BH_O + boff;
        const uint32_t bbm = rb + BM_O + boff;

        #pragma unroll
        for (int kk = 0; kk < 8; ++kk) {
            const uint32_t kb = kk * 32;
            uint32_t ah[4], am[4];
            uint32_t bh01[4], bh23[4], bm01[4], bm23[4];
            ldsm4(ah, abh + kb);
            ldsm4(am, abm + kb);
            ldsm4(bh01, bbh + kb);
            ldsm4(bh23, bbh + 16 * A_STR + kb);
            ldsm4(bm01, bbm + kb);
            ldsm4(bm23, bbm + 16 * A_STR + kb);
            const uint32_t* bhv[4] = {bh01, bh01 + 2, bh23, bh23 + 2};
            const uint32_t* bmv[4] = {bm01, bm01 + 2, bm23, bm23 + 2};
            #pragma unroll
            for (int ni = 0; ni < 4; ++ni) mma16816(acc[ni], ah, bhv[ni]);
            #pragma unroll
            for (int ni = 0; ni < 4; ++ni) mma16816(acc[ni], ah, bmv[ni]);
            #pragma unroll
            for (int ni = 0; ni < 4; ++ni) mma16816(acc[ni], am, bhv[ni]);
        }

        if (s + 1 < NSTAGE) {
            #pragma unroll
            for (int g = 0; g < 4; ++g) {
                float4 a = cx[2 * g], c = cx[2 * g + 1];
                float f[8] = {a.x, a.y, a.z, a.w, c.x, c.y, c.z, c.w};
                uint32_t hp[4], mp[4];
                #pragma unroll
                for (int i = 0; i < 4; ++i) {
                    float f0 = f[2 * i], f1 = f[2 * i + 1];
                    uint32_t h2 = cvt_h2(f0, f1);
                    __half2 hh = *(__half2*)&h2;
                    float2 bk = __half22float2(hh);
                    mp[i] = cvt_h2(f0 - bk.x, f1 - bk.y);
                    hp[i] = h2;
                    ls  += f0 + f1;
                    lss  = fmaf(f0, f0, fmaf(f1, f1, lss));
                }
                *(uint4*)(wbuf + AH_O + a_sts + g * 16) = make_uint4(hp[0], hp[1], hp[2], hp[3]);
                *(uint4*)(wbuf + AM_O + a_sts + g * 16) = make_uint4(mp[0], mp[1], mp[2], mp[3]);
            }
        }

        if (s + 2 < NSTAGE) {
            #pragma unroll
            for (int j = 0; j < 8; ++j) cx[j] = xp[(s + 2) * 32 + j];
        }

        CP_WAIT0();
        __syncthreads();
    }

    // ---- LN stats (reduce over 4 lanes per row) ----
    ls  += __shfl_xor_sync(0xffffffffu, ls, 1);
    ls  += __shfl_xor_sync(0xffffffffu, ls, 2);
    lss += __shfl_xor_sync(0xffffffffu, lss, 1);
    lss += __shfl_xor_sync(0xffffffffu, lss, 2);
    if (p4 == 0) {
        float mu  = ls * (1.f / D_MODEL);
        float var = lss * (1.f / D_MODEL) - mu * mu;
        ((float*)(smb + MU_O))[pr] = mu;
        ((float*)(smb + RS_O))[pr] = rsqrtf(var + LN_EPS);
    }
    __syncthreads();

    // ---- dump raw dot products to smem logits tile [128][68] ----
    float* lgs = (float*)smb;
    #pragma unroll
    for (int ni = 0; ni < 4; ++ni) {
        int row = wm * 16 + (lane >> 2);
        int col = wn * 32 + ni * 8 + (lane & 3) * 2;
        lgs[row * 68 + col]           = acc[ni][0];
        lgs[row * 68 + col + 1]       = acc[ni][1];
        lgs[(row + 8) * 68 + col]     = acc[ni][2];
        lgs[(row + 8) * 68 + col + 1] = acc[ni][3];
    }
    __syncthreads();

    // ---- per-row epilogue ----
    if (t < TM) {
        const float mu = ((float*)(smb + MU_O))[t];
        const float rs = ((float*)(smb + RS_O))[t];
        const float* c1 = (const float*)(smb + C1_O);
        const float* c2 = (const float*)(smb + C2_O);
        float* lrow = lgs + t * 68;

        float mx = -1e30f, v0 = -1e30f, v1 = -1e30f;
        int i0 = 0, i1 = 0;
        #pragma unroll 8
        for (int e = 0; e < 64; ++e) {
            float v = fmaf(-mu, c1[e], lrow[e]) * rs + c2[e];
            lrow[e] = v;
            mx = fmaxf(mx, v);
            if (v > v0)      { v1 = v0; i1 = i0; v0 = v; i0 = e; }
            else if (v > v1) { v1 = v; i1 = e; }
        }
        float sum = 0.f;
        #pragma unroll 8
        for (int e = 0; e < 64; ++e) {
            float ev = __expf(lrow[e] - mx);
            lrow[e] = ev;
            sum += ev;
        }
        float inv = 1.f / sum;
        float sw0 = __expf(v0 - mx) * inv;
        float sw1 = __expf(v1 - mx) * inv;
        float rn  = 1.f / (sw0 + sw1 + 1e-8f);
        float o0 = sw0 * rn, o1 = sw1 * rn;

        int grow = row0 + t;
        float* orow = out + (size_t)grow * 64;
        #pragma unroll
        for (int e = 0; e < 64; e += 4) {
            float w0 = lrow[e + 0] * inv;
            float w1 = lrow[e + 1] * inv;
            float w2 = lrow[e + 2] * inv;
            float w3 = lrow[e + 3] * inv;
            lrow[e + 0] = w0; lrow[e + 1] = w1;
            lrow[e + 2] = w2; lrow[e + 3] = w3;
            float4 o;
            o.x = (e + 0 == i0) ? o0 : ((e + 0 == i1) ? o1 : 0.f);
            o.y = (e + 1 == i0) ? o0 : ((e + 1 == i1) ? o1 : 0.f);
            o.z = (e + 2 == i0) ? o0 : ((e + 2 == i1) ? o1 : 0.f);
            o.w = (e + 3 == i0) ? o0 : ((e + 3 == i1) ? o1 : 0.f);
            *(float4*)(orow + e) = o;
        }
        out[OUT_IDX_OFF + (size_t)grow * 2 + 0] = (float)i0;
        out[OUT_IDX_OFF + (size_t)grow * 2 + 1] = (float)i1;
    }
    __syncthreads();

    // ---- deterministic per-CTA lb partials ----
    if (t < N_EXP) {
        float s = 0.f;
        #pragma unroll 8
        for (int r = 0; r < TM; ++r) s += lgs[r * 68 + t];
        g_part[blockIdx.x * N_EXP + t] = s;
    }
}

// ================= final: load-balance loss =================
__global__ void final_kernel(float* __restrict__ out) {
    __shared__ float sh[N_EXP];
    int t = threadIdx.x;  // 64 threads
    float s = 0.f;
    for (int c = 0; c < NCTA; ++c) s += g_part[c * N_EXP + t];
    float mean = s * (1.f / ROWS);
    sh[t] = -mean * logf(mean + 1e-8f);
    __syncthreads();
    if (t == 0) {
        float acc = 0.f;
        for (int i = 0; i < N_EXP; ++i) acc += sh[i];
        out[OUT_LB_OFF] = acc;
    }
}

extern "C" void kernel_launch(void* const* d_in, const int* in_sizes, int n_in,
                              void* d_out, int out_size) {
    const float* x     = (const float*)d_in[0];
    const float* gamma = (const float*)d_in[1];
    const float* beta  = (const float*)d_in[2];
    const float* W     = (const float*)d_in[3];
    const float* b     = (const float*)d_in[4];
    float* out = (float*)d_out;

    cudaFuncSetAttribute(main_kernel, cudaFuncAttributeMaxDynamicSharedMemorySize, SMEM_REQ);

    prep_kernel<<<256, 256>>>(W, gamma, beta, b);
    main_kernel<<<NCTA, THREADS, SMEM_REQ>>>(x, out);
    final_kernel<<<1, N_EXP>>>(out);
}

// round 9
// speedup vs baseline: 1.4459x; 1.4459x over previous
#include <cuda_runtime.h>
#include <cuda_fp16.h>
#include <math.h>
#include <stdint.h>

#define D_MODEL 4096
#define N_EXP   64
#define ROWS    16384          // 4 * 4096
#define LN_EPS  1e-5f
#define TM      128            // rows per CTA
#define NSTAGE  64             // K chunks of 64
#define NCTA    (ROWS / TM)    // 128
#define THREADS 512

// Output layout (fp32 flat): sparse_w[16384*64], indices[16384*2] as float, lb_loss
#define OUT_IDX_OFF 1048576
#define OUT_LB_OFF  1081344

// ---- dynamic smem layout (identical to the 131us kernel) ----
#define A_STR 144
#define B_STR 144
#define AH_O  0
#define AM_O  18432
#define BH_O  36864
#define BM_O  46080
#define BUFB  55296
#define EXT   (2 * BUFB)          // 110592
#define MU_O  (EXT)
#define RS_O  (EXT + 512)
#define C1_O  (EXT + 1024)
#define C2_O  (EXT + 1280)
#define SMEM_REQ (EXT + 1536)     // 112128 bytes

// ---- device scratch ----
__device__ __align__(16) __half g_wh[N_EXP * D_MODEL];  // high fp16 part of gamma*W
__device__ __align__(16) __half g_wm[N_EXP * D_MODEL];  // mid  fp16 part
__device__ float g_c1p[256];
__device__ float g_c2p[256];
__device__ float g_part[NCTA * N_EXP];

// ================= PTX helpers =================
__device__ __forceinline__ uint32_t smem_u32(const void* p) {
    uint32_t a;
    asm("{ .reg .u64 t; cvta.to.shared.u64 t, %1; cvt.u32.u64 %0, t; }" : "=r"(a) : "l"(p));
    return a;
}
__device__ __forceinline__ void ldsm4(uint32_t* r, uint32_t addr) {
    asm volatile("ldmatrix.sync.aligned.m8n8.x4.shared.b16 {%0,%1,%2,%3}, [%4];"
                 : "=r"(r[0]), "=r"(r[1]), "=r"(r[2]), "=r"(r[3]) : "r"(addr));
}
__device__ __forceinline__ void mma16816(float* c, const uint32_t* a, const uint32_t* b) {
    asm volatile(
        "mma.sync.aligned.m16n8k16.row.col.f32.f16.f16.f32 "
        "{%0,%1,%2,%3}, {%4,%5,%6,%7}, {%8,%9}, {%0,%1,%2,%3};"
        : "+f"(c[0]), "+f"(c[1]), "+f"(c[2]), "+f"(c[3])
        : "r"(a[0]), "r"(a[1]), "r"(a[2]), "r"(a[3]), "r"(b[0]), "r"(b[1]));
}
__device__ __forceinline__ uint32_t cvt_h2(float lo, float hi) {
    uint32_t r;
    asm("cvt.rn.f16x2.f32 %0, %1, %2;" : "=r"(r) : "f"(hi), "f"(lo));
    return r;
}
__device__ __forceinline__ void cpa16(uint32_t dst, const __half* src) {
    uint64_t g;
    asm("cvta.to.global.u64 %0, %1;" : "=l"(g) : "l"(src));
    asm volatile("cp.async.cg.shared.global [%0], [%1], 16;" :: "r"(dst), "l"(g) : "memory");
}
#define CP_COMMIT() asm volatile("cp.async.commit_group;" ::: "memory")
#define CP_WAIT0()  asm volatile("cp.async.wait_group 0;" ::: "memory")

// ================= prep: split gamma*W into fp16 h/m parts + partial c1/c2 =================
__global__ void prep_kernel(const float* __restrict__ W,
                            const float* __restrict__ gamma,
                            const float* __restrict__ beta,
                            const float* __restrict__ b) {
    int blk = blockIdx.x;          // 256 blocks: expert e = blk>>2, quarter q = blk&3
    int e = blk >> 2, q = blk & 3;
    int t = threadIdx.x;           // 256
    float a1 = 0.f, a2 = 0.f;
    #pragma unroll
    for (int i = 0; i < 4; ++i) {
        int k = q * 1024 + i * 256 + t;
        float w  = W[e * D_MODEL + k];
        float gw = gamma[k] * w;
        a1 += gw;
        a2 += beta[k] * w;
        __half h = __float2half_rn(gw);
        float  r = gw - __half2float(h);
        __half m = __float2half_rn(r);
        g_wh[e * D_MODEL + k] = h;
        g_wm[e * D_MODEL + k] = m;
    }
    __shared__ float s1[8], s2[8];
    #pragma unroll
    for (int o = 16; o > 0; o >>= 1) {
        a1 += __shfl_xor_sync(0xffffffffu, a1, o);
        a2 += __shfl_xor_sync(0xffffffffu, a2, o);
    }
    if ((t & 31) == 0) { s1[t >> 5] = a1; s2[t >> 5] = a2; }
    __syncthreads();
    if (t == 0) {
        float v1 = 0.f, v2 = 0.f;
        #pragma unroll
        for (int i = 0; i < 8; ++i) { v1 += s1[i]; v2 += s2[i]; }
        g_c1p[blk] = v1;
        g_c2p[blk] = v2 + (q == 0 ? b[e] : 0.f);
    }
}

// ================= main fused kernel =================
extern __shared__ char smem_dyn[];

__global__ __launch_bounds__(THREADS, 1)
void main_kernel(const float* __restrict__ x, float* __restrict__ out) {
    char* smb = smem_dyn;
    const uint32_t sbase = smem_u32(smb);
    const int t    = threadIdx.x;
    const int lane = t & 31;
    const int wid  = t >> 5;
    const int wm   = wid & 7;       // M block (16 rows)
    const int wn   = wid >> 3;      // N block (32 cols)
    const int row0 = blockIdx.x * TM;

    if (t < 64) {
        float c1 = g_c1p[4 * t] + g_c1p[4 * t + 1] + g_c1p[4 * t + 2] + g_c1p[4 * t + 3];
        float c2 = g_c2p[4 * t] + g_c2p[4 * t + 1] + g_c2p[4 * t + 2] + g_c2p[4 * t + 3];
        ((float*)(smb + C1_O))[t] = c1;
        ((float*)(smb + C2_O))[t] = c2;
    }

    // producer mapping: 4 threads per row (16 cols each)
    const int pr = t >> 2, p4 = t & 3;
    const float4* xp  = (const float4*)(x + (size_t)(row0 + pr) * D_MODEL + p4 * 16);
    // B cp.async mapping: 8 threads per expert row, 16B each per part per stage
    const int be = t >> 3, bc = t & 7;
    const __half* bsrc_h = g_wh + (size_t)be * D_MODEL + bc * 8;
    const __half* bsrc_m = g_wm + (size_t)be * D_MODEL + bc * 8;
    const uint32_t bdst = (uint32_t)(be * B_STR + bc * 16);

    // ldmatrix lane offsets
    const uint32_t aoff = (uint32_t)((wm * 16 + (lane & 15)) * A_STR + (lane >> 4) * 16);
    const uint32_t boff = (uint32_t)((wn * 32 + ((lane >> 4) & 1) * 8 + (lane & 7)) * B_STR
                                     + ((lane >> 3) & 1) * 16);
    const uint32_t a_sts = (uint32_t)(pr * A_STR + p4 * 32);

    float acc[4][4];
    #pragma unroll
    for (int ni = 0; ni < 4; ++ni)
        #pragma unroll
        for (int q = 0; q < 4; ++q) acc[ni][q] = 0.f;

    float ls = 0.f, lss = 0.f;
    float4 cx[4];

    // ---- prologue: B(0) cp.async, x(0) split+STS into buf0, prefetch x(1) ----
    {
        cpa16(sbase + BH_O + bdst, bsrc_h);
        cpa16(sbase + BM_O + bdst, bsrc_m);
        CP_COMMIT();

        #pragma unroll
        for (int j = 0; j < 4; ++j) cx[j] = xp[j];
        char* bb = smb;
        #pragma unroll
        for (int g = 0; g < 2; ++g) {
            float4 a = cx[2 * g], c = cx[2 * g + 1];
            float f[8] = {a.x, a.y, a.z, a.w, c.x, c.y, c.z, c.w};
            uint32_t hp[4], mp[4];
            #pragma unroll
            for (int i = 0; i < 4; ++i) {
                float f0 = f[2 * i], f1 = f[2 * i + 1];
                uint32_t h2 = cvt_h2(f0, f1);
                __half2 hh = *(__half2*)&h2;
                float2 bk = __half22float2(hh);
                mp[i] = cvt_h2(f0 - bk.x, f1 - bk.y);
                hp[i] = h2;
                ls  += f0 + f1;
                lss  = fmaf(f0, f0, fmaf(f1, f1, lss));
            }
            *(uint4*)(bb + AH_O + a_sts + g * 16) = make_uint4(hp[0], hp[1], hp[2], hp[3]);
            *(uint4*)(bb + AM_O + a_sts + g * 16) = make_uint4(mp[0], mp[1], mp[2], mp[3]);
        }
        #pragma unroll
        for (int j = 0; j < 4; ++j) cx[j] = xp[16 + j];
        CP_WAIT0();
    }
    __syncthreads();

    // ---- main loop: cp.async B(s+1) || MMA(s) || split+STS x(s+1) || LDG x(s+2) ----
    for (int s = 0; s < NSTAGE; ++s) {
        const uint32_t rb = sbase + (uint32_t)((s & 1) * BUFB);
        const uint32_t wb = sbase + (uint32_t)(((s + 1) & 1) * BUFB);
        char* wbuf = smb + ((s + 1) & 1) * BUFB;

        if (s + 1 < NSTAGE) {
            cpa16(wb + BH_O + bdst, bsrc_h + (s + 1) * 64);
            cpa16(wb + BM_O + bdst, bsrc_m + (s + 1) * 64);
            CP_COMMIT();
        }

        const uint32_t abh = rb + AH_O + aoff;
        const uint32_t abm = rb + AM_O + aoff;
        const uint32_t bbh = rb + BH_O + boff;
        const uint32_t bbm = rb + BM_O + boff;

        #pragma unroll
        for (int kk = 0; kk < 4; ++kk) {
            const uint32_t kb = kk * 32;
            uint32_t ah[4], am[4];
            uint32_t bh01[4], bh23[4], bm01[4], bm23[4];
            ldsm4(ah, abh + kb);
            ldsm4(am, abm + kb);
            ldsm4(bh01, bbh + kb);
            ldsm4(bh23, bbh + 2304 + kb);
            ldsm4(bm01, bbm + kb);
            ldsm4(bm23, bbm + 2304 + kb);
            const uint32_t* bhv[4] = {bh01, bh01 + 2, bh23, bh23 + 2};
            const uint32_t* bmv[4] = {bm01, bm01 + 2, bm23, bm23 + 2};
            // product-major: accumulator reuse distance = 4 MMAs
            #pragma unroll
            for (int ni = 0; ni < 4; ++ni) mma16816(acc[ni], ah, bhv[ni]);
            #pragma unroll
            for (int ni = 0; ni < 4; ++ni) mma16816(acc[ni], ah, bmv[ni]);
            #pragma unroll
            for (int ni = 0; ni < 4; ++ni) mma16816(acc[ni], am, bhv[ni]);
        }

        if (s + 1 < NSTAGE) {
            #pragma unroll
            for (int g = 0; g < 2; ++g) {
                float4 a = cx[2 * g], c = cx[2 * g + 1];
                float f[8] = {a.x, a.y, a.z, a.w, c.x, c.y, c.z, c.w};
                uint32_t hp[4], mp[4];
                #pragma unroll
                for (int i = 0; i < 4; ++i) {
                    float f0 = f[2 * i], f1 = f[2 * i + 1];
                    uint32_t h2 = cvt_h2(f0, f1);
                    __half2 hh = *(__half2*)&h2;
                    float2 bk = __half22float2(hh);
                    mp[i] = cvt_h2(f0 - bk.x, f1 - bk.y);
                    hp[i] = h2;
                    ls  += f0 + f1;
                    lss  = fmaf(f0, f0, fmaf(f1, f1, lss));
                }
                *(uint4*)(wbuf + AH_O + a_sts + g * 16) = make_uint4(hp[0], hp[1], hp[2], hp[3]);
                *(uint4*)(wbuf + AM_O + a_sts + g * 16) = make_uint4(mp[0], mp[1], mp[2], mp[3]);
            }
        }

        if (s + 2 < NSTAGE) {
            #pragma unroll
            for (int j = 0; j < 4; ++j) cx[j] = xp[(s + 2) * 16 + j];
        }

        CP_WAIT0();
        __syncthreads();
    }

    // ---- LN stats (reduce over 4 lanes per row) ----
    ls  += __shfl_xor_sync(0xffffffffu, ls, 1);
    ls  += __shfl_xor_sync(0xffffffffu, ls, 2);
    lss += __shfl_xor_sync(0xffffffffu, lss, 1);
    lss += __shfl_xor_sync(0xffffffffu, lss, 2);
    if (p4 == 0) {
        float mu  = ls * (1.f / D_MODEL);
        float var = lss * (1.f / D_MODEL) - mu * mu;
        ((float*)(smb + MU_O))[pr] = mu;
        ((float*)(smb + RS_O))[pr] = rsqrtf(var + LN_EPS);
    }
    __syncthreads();

    // ---- dump raw dot products to smem logits tile [128][68] ----
    float* lgs = (float*)smb;
    #pragma unroll
    for (int ni = 0; ni < 4; ++ni) {
        int row = wm * 16 + (lane >> 2);
        int col = wn * 32 + ni * 8 + (lane & 3) * 2;
        lgs[row * 68 + col]           = acc[ni][0];
        lgs[row * 68 + col + 1]       = acc[ni][1];
        lgs[(row + 8) * 68 + col]     = acc[ni][2];
        lgs[(row + 8) * 68 + col + 1] = acc[ni][3];
    }
    __syncthreads();

    // ---- per-row epilogue ----
    if (t < TM) {
        const float mu = ((float*)(smb + MU_O))[t];
        const float rs = ((float*)(smb + RS_O))[t];
        const float* c1 = (const float*)(smb + C1_O);
        const float* c2 = (const float*)(smb + C2_O);
        float* lrow = lgs + t * 68;

        float mx = -1e30f, v0 = -1e30f, v1 = -1e30f;
        int i0 = 0, i1 = 0;
        #pragma unroll 8
        for (int e = 0; e < 64; ++e) {
            float v = fmaf(-mu, c1[e], lrow[e]) * rs + c2[e];
            lrow[e] = v;
            mx = fmaxf(mx, v);
            if (v > v0)      { v1 = v0; i1 = i0; v0 = v; i0 = e; }
            else if (v > v1) { v1 = v; i1 = e; }
        }
        float sum = 0.f;
        #pragma unroll 8
        for (int e = 0; e < 64; ++e) {
            float ev = __expf(lrow[e] - mx);
            lrow[e] = ev;
            sum += ev;
        }
        float inv = 1.f / sum;
        float sw0 = __expf(v0 - mx) * inv;
        float sw1 = __expf(v1 - mx) * inv;
        float rn  = 1.f / (sw0 + sw1 + 1e-8f);
        float o0 = sw0 * rn, o1 = sw1 * rn;

        int grow = row0 + t;
        float* orow = out + (size_t)grow * 64;
        #pragma unroll
        for (int e = 0; e < 64; e += 4) {
            float w0 = lrow[e + 0] * inv;
            float w1 = lrow[e + 1] * inv;
            float w2 = lrow[e + 2] * inv;
            float w3 = lrow[e + 3] * inv;
            lrow[e + 0] = w0; lrow[e + 1] = w1;
            lrow[e + 2] = w2; lrow[e + 3] = w3;
            float4 o;
            o.x = (e + 0 == i0) ? o0 : ((e + 0 == i1) ? o1 : 0.f);
            o.y = (e + 1 == i0) ? o0 : ((e + 1 == i1) ? o1 : 0.f);
            o.z = (e + 2 == i0) ? o0 : ((e + 2 == i1) ? o1 : 0.f);
            o.w = (e + 3 == i0) ? o0 : ((e + 3 == i1) ? o1 : 0.f);
            *(float4*)(orow + e) = o;
        }
        out[OUT_IDX_OFF + (size_t)grow * 2 + 0] = (float)i0;
        out[OUT_IDX_OFF + (size_t)grow * 2 + 1] = (float)i1;
    }
    __syncthreads();

    // ---- deterministic per-CTA lb partials ----
    if (t < N_EXP) {
        float s = 0.f;
        #pragma unroll 8
        for (int r = 0; r < TM; ++r) s += lgs[r * 68 + t];
        g_part[blockIdx.x * N_EXP + t] = s;
    }
}

// ================= final: load-balance loss =================
__global__ void final_kernel(float* __restrict__ out) {
    __shared__ float sh[N_EXP];
    int t = threadIdx.x;  // 64 threads
    float s = 0.f;
    for (int c = 0; c < NCTA; ++c) s += g_part[c * N_EXP + t];
    float mean = s * (1.f / ROWS);
    sh[t] = -mean * logf(mean + 1e-8f);
    __syncthreads();
    if (t == 0) {
        float acc = 0.f;
        for (int i = 0; i < N_EXP; ++i) acc += sh[i];
        out[OUT_LB_OFF] = acc;
    }
}

extern "C" void kernel_launch(void* const* d_in, const int* in_sizes, int n_in,
                              void* d_out, int out_size) {
    const float* x     = (const float*)d_in[0];
    const float* gamma = (const float*)d_in[1];
    const float* beta  = (const float*)d_in[2];
    const float* W     = (const float*)d_in[3];
    const float* b     = (const float*)d_in[4];
    float* out = (float*)d_out;

    cudaFuncSetAttribute(main_kernel, cudaFuncAttributeMaxDynamicSharedMemorySize, SMEM_REQ);

    prep_kernel<<<256, 256>>>(W, gamma, beta, b);
    main_kernel<<<NCTA, THREADS, SMEM_REQ>>>(x, out);
    final_kernel<<<1, N_EXP>>>(out);
}